// round 1
// baseline (speedup 1.0000x reference)
#include <cuda_runtime.h>

#define Bn 32
#define Cn 32
#define Gn 4096
#define Nn 16384
#define Hn 64
#define TPB 256
#define PPT 2
#define PPB (TPB * PPT)   // 512 points per block

// scratch: slot -> cell index (monotone per batch)
__device__ int g_idx[Bn * Nn];

// ---------------------------------------------------------------------------
// Kernel 1: per-batch cumsum of counts + searchsorted(right) for every slot.
// One block per batch, 256 threads, 16 counts per thread.
// ---------------------------------------------------------------------------
__global__ __launch_bounds__(TPB) void prep_kernel(const int* __restrict__ counts)
{
    const int b = blockIdx.x;
    __shared__ int cum[Gn];
    __shared__ int wsum[8];

    const int t    = threadIdx.x;
    const int lane = t & 31;
    const int w    = t >> 5;
    const int base = t * 16;

    int local[16];
    int s = 0;
#pragma unroll
    for (int i = 0; i < 16; i++) {
        s += counts[b * Gn + base + i];
        local[i] = s;
    }
    // inclusive warp scan of per-thread sums
    int v = s;
#pragma unroll
    for (int d = 1; d < 32; d <<= 1) {
        int u = __shfl_up_sync(0xffffffff, v, d);
        if (lane >= d) v += u;
    }
    if (lane == 31) wsum[w] = v;
    __syncthreads();
    int woff = 0;
    for (int i = 0; i < w; i++) woff += wsum[i];
    const int excl = woff + v - s;   // exclusive prefix for this thread's chunk
#pragma unroll
    for (int i = 0; i < 16; i++) cum[base + i] = local[i] + excl;
    __syncthreads();

    // searchsorted(cum, j, side='right'): first index with cum[idx] > j
    for (int j = t; j < Nn; j += TPB) {
        int lo = 0, hi = Gn;
        while (lo < hi) {
            int mid = (lo + hi) >> 1;
            if (cum[mid] > j) hi = mid; else lo = mid + 1;
        }
        g_idx[b * Nn + j] = lo;
    }
}

// ---------------------------------------------------------------------------
// Kernel 2: gather + MLP + offsets + reg. 2 points/thread to amortize weight
// LDS over 2 FFMAs.
// ---------------------------------------------------------------------------
__global__ __launch_bounds__(TPB) void mlp_kernel(
    const float* __restrict__ x,       // (B, C, G)
    const float* __restrict__ b_rnd,   // (B, 2, N)
    const float* __restrict__ grid_o,  // (3, G)
    const float* __restrict__ W1,      // (H, C+2)
    const float* __restrict__ b1,      // (H)
    const float* __restrict__ W2,      // (3, H)
    const float* __restrict__ b2,      // (3)
    float* __restrict__ out,           // (B, 3, N)
    float* __restrict__ reg_out)       // (B, N)
{
    __shared__ float W1s[Hn * 34];
    __shared__ float b1s[Hn];
    __shared__ float W2s[3 * Hn];
    __shared__ float b2s[3];

    const int t = threadIdx.x;
    for (int i = t; i < Hn * 34; i += TPB) W1s[i] = W1[i];
    if (t < Hn)     b1s[t] = b1[t];
    if (t < 3 * Hn) W2s[t] = W2[t];
    if (t < 3)      b2s[t] = b2[t];
    __syncthreads();

    const int blocksPerBatch = Nn / PPB;            // 32
    const int b    = blockIdx.x / blocksPerBatch;
    const int tile = blockIdx.x % blocksPerBatch;
    const int j0   = tile * PPB + t;                // point A
    const int j1   = j0 + TPB;                      // point B

    const int i0 = g_idx[b * Nn + j0];
    const int i1 = g_idx[b * Nn + j1];

    float v0[34], v1[34];
    const float* xb = x + (size_t)b * Cn * Gn;
#pragma unroll
    for (int c = 0; c < Cn; c++) {
        v0[c] = __ldg(xb + c * Gn + i0);
        v1[c] = __ldg(xb + c * Gn + i1);
    }
    const float* br = b_rnd + (size_t)b * 2 * Nn;
    v0[32] = br[j0];       v0[33] = br[Nn + j0];
    v1[32] = br[j1];       v1[33] = br[Nn + j1];

    float o0a = b2s[0], o1a = b2s[1], o2a = b2s[2];
    float o0b = b2s[0], o1b = b2s[1], o2b = b2s[2];

#pragma unroll 4
    for (int h = 0; h < Hn; h++) {
        float a0 = b1s[h], a1 = b1s[h];
        const float* wrow = &W1s[h * 34];
#pragma unroll
        for (int c = 0; c < 34; c++) {
            float wv = wrow[c];
            a0 = fmaf(wv, v0[c], a0);
            a1 = fmaf(wv, v1[c], a1);
        }
        a0 = fmaxf(a0, 0.f);
        a1 = fmaxf(a1, 0.f);
        const float w0 = W2s[h], w1 = W2s[Hn + h], w2 = W2s[2 * Hn + h];
        o0a = fmaf(w0, a0, o0a); o1a = fmaf(w1, a0, o1a); o2a = fmaf(w2, a0, o2a);
        o0b = fmaf(w0, a1, o0b); o1b = fmaf(w1, a1, o1b); o2b = fmaf(w2, a1, o2b);
    }

    const float thr = 0.10825317547305482f;  // sqrt(3)/16
    const float n0 = sqrtf(o0a * o0a + o1a * o1a + o2a * o2a);
    const float n1 = sqrtf(o0b * o0b + o1b * o1b + o2b * o2b);

    float* outb = out + (size_t)b * 3 * Nn;
    outb[j0]          = o0a + grid_o[i0];
    outb[Nn + j0]     = o1a + grid_o[Gn + i0];
    outb[2 * Nn + j0] = o2a + grid_o[2 * Gn + i0];
    outb[j1]          = o0b + grid_o[i1];
    outb[Nn + j1]     = o1b + grid_o[Gn + i1];
    outb[2 * Nn + j1] = o2b + grid_o[2 * Gn + i1];

    reg_out[b * Nn + j0] = fmaxf(n0 - thr, 0.f);
    reg_out[b * Nn + j1] = fmaxf(n1 - thr, 0.f);
}

extern "C" void kernel_launch(void* const* d_in, const int* in_sizes, int n_in,
                              void* d_out, int out_size)
{
    const float* x      = (const float*)d_in[0];
    const int*   counts = (const int*)  d_in[1];
    const float* b_rnd  = (const float*)d_in[2];
    const float* grid_o = (const float*)d_in[3];
    const float* W1     = (const float*)d_in[4];
    const float* b1     = (const float*)d_in[5];
    const float* W2     = (const float*)d_in[6];
    const float* b2     = (const float*)d_in[7];

    float* out     = (float*)d_out;              // (B, 3, N)
    float* reg_out = out + (size_t)Bn * 3 * Nn;  // (B, N)

    prep_kernel<<<Bn, TPB>>>(counts);
    mlp_kernel<<<Bn * (Nn / PPB), TPB>>>(x, b_rnd, grid_o, W1, b1, W2, b2,
                                         out, reg_out);
}

// round 2
// speedup vs baseline: 1.3456x; 1.3456x over previous
#include <cuda_runtime.h>

#define Bn 32
#define Cn 32
#define Gn 4096
#define Nn 16384
#define Hn 64
#define TPB 256
#define PPT 2
#define PPB (TPB * PPT)   // 512 points per block

typedef unsigned long long u64;

// per-batch inclusive cumsum of counts
__device__ int g_cum[Bn * Gn];

// ---- packed f32x2 helpers (Blackwell FFMA2; ptxas never auto-fuses) -------
static __device__ __forceinline__ u64 pk(float lo, float hi) {
    u64 r; asm("mov.b64 %0, {%1, %2};" : "=l"(r) : "f"(lo), "f"(hi)); return r;
}
static __device__ __forceinline__ void upk(float& lo, float& hi, u64 v) {
    asm("mov.b64 {%0, %1}, %2;" : "=f"(lo), "=f"(hi) : "l"(v));
}
static __device__ __forceinline__ u64 fma2(u64 a, u64 b, u64 c) {
    u64 d; asm("fma.rn.f32x2 %0, %1, %2, %3;" : "=l"(d) : "l"(a), "l"(b), "l"(c));
    return d;
}

// ---------------------------------------------------------------------------
// Kernel 1: per-batch inclusive cumsum of counts -> g_cum. One block/batch.
// ---------------------------------------------------------------------------
__global__ __launch_bounds__(TPB) void prep_kernel(const int* __restrict__ counts)
{
    const int b = blockIdx.x;
    __shared__ int wsum[8];

    const int t    = threadIdx.x;
    const int lane = t & 31;
    const int w    = t >> 5;
    const int base = t * 16;

    int local[16];
    int s = 0;
#pragma unroll
    for (int i = 0; i < 16; i++) {
        s += counts[b * Gn + base + i];
        local[i] = s;
    }
    int v = s;
#pragma unroll
    for (int d = 1; d < 32; d <<= 1) {
        int u = __shfl_up_sync(0xffffffff, v, d);
        if (lane >= d) v += u;
    }
    if (lane == 31) wsum[w] = v;
    __syncthreads();
    int woff = 0;
    for (int i = 0; i < w; i++) woff += wsum[i];
    const int excl = woff + v - s;
#pragma unroll
    for (int i = 0; i < 16; i++) g_cum[b * Gn + base + i] = local[i] + excl;
}

// ---------------------------------------------------------------------------
// Kernel 2: searchsorted (shared cum) + gather + packed-f32x2 MLP + epilogue.
// ---------------------------------------------------------------------------
__global__ __launch_bounds__(TPB) void mlp_kernel(
    const float* __restrict__ x,       // (B, C, G)
    const float* __restrict__ b_rnd,   // (B, 2, N)
    const float* __restrict__ grid_o,  // (3, G)
    const float* __restrict__ W1,      // (H, C+2)
    const float* __restrict__ b1,      // (H)
    const float* __restrict__ W2,      // (3, H)
    const float* __restrict__ b2,      // (3)
    float* __restrict__ out,           // (B, 3, N)
    float* __restrict__ reg_out)       // (B, N)
{
    __shared__ int cums[Gn];                        // 16 KB
    __shared__ __align__(16) float W1s[Hn * 34];    // 8.7 KB, row stride 136B (8B-aligned)
    __shared__ float b1s[Hn];
    __shared__ u64  W2d[3 * Hn];                    // duplicated-lane W2

    const int t = threadIdx.x;
    const int blocksPerBatch = Nn / PPB;            // 32
    const int b    = blockIdx.x / blocksPerBatch;
    const int tile = blockIdx.x % blocksPerBatch;

    for (int i = t; i < Hn * 34; i += TPB) W1s[i] = W1[i];
    if (t < Hn) b1s[t] = b1[t];
    if (t < 3 * Hn) { float wv = W2[t]; W2d[t] = pk(wv, wv); }
#pragma unroll
    for (int i = t; i < Gn; i += TPB) cums[i] = g_cum[b * Gn + i];
    __syncthreads();

    const int j0 = tile * PPB + t;                  // point A
    const int j1 = j0 + TPB;                        // point B

    // searchsorted(cum, j, 'right'): first idx with cum[idx] > j
    int i0, i1;
    {
        int lo = 0, hi = Gn;
        while (lo < hi) { int m = (lo + hi) >> 1; if (cums[m] > j0) hi = m; else lo = m + 1; }
        i0 = lo;
        lo = 0; hi = Gn;
        while (lo < hi) { int m = (lo + hi) >> 1; if (cums[m] > j1) hi = m; else lo = m + 1; }
        i1 = lo;
    }

    // gather inputs, packed over channel pairs: vp[c] = {feat[2c], feat[2c+1]}
    u64 vp0[17], vp1[17];
    const float* xb = x + (size_t)b * Cn * Gn;
#pragma unroll
    for (int c = 0; c < 16; c++) {
        vp0[c] = pk(__ldg(xb + (2 * c) * Gn + i0), __ldg(xb + (2 * c + 1) * Gn + i0));
        vp1[c] = pk(__ldg(xb + (2 * c) * Gn + i1), __ldg(xb + (2 * c + 1) * Gn + i1));
    }
    const float* br = b_rnd + (size_t)b * 2 * Nn;
    vp0[16] = pk(br[j0], br[Nn + j0]);
    vp1[16] = pk(br[j1], br[Nn + j1]);

    const float bb0 = __ldg(b2 + 0), bb1 = __ldg(b2 + 1), bb2 = __ldg(b2 + 2);
    u64 oX = pk(bb0, bb0);   // {o0 of point A, o0 of point B}
    u64 oY = pk(bb1, bb1);
    u64 oZ = pk(bb2, bb2);

#pragma unroll 4
    for (int h = 0; h < Hn; h++) {
        const u64* wrow = reinterpret_cast<const u64*>(&W1s[h * 34]);
        u64 acc0 = 0ull, acc1 = 0ull;
#pragma unroll
        for (int c = 0; c < 17; c++) {
            u64 wv = wrow[c];
            acc0 = fma2(wv, vp0[c], acc0);
            acc1 = fma2(wv, vp1[c], acc1);
        }
        float l0, h0, l1, h1;
        upk(l0, h0, acc0);
        upk(l1, h1, acc1);
        float a0 = fmaxf(l0 + h0 + b1s[h], 0.f);
        float a1 = fmaxf(l1 + h1 + b1s[h], 0.f);
        u64 act = pk(a0, a1);
        oX = fma2(W2d[h], act, oX);
        oY = fma2(W2d[Hn + h], act, oY);
        oZ = fma2(W2d[2 * Hn + h], act, oZ);
    }

    float o0a, o0b, o1a, o1b, o2a, o2b;
    upk(o0a, o0b, oX);
    upk(o1a, o1b, oY);
    upk(o2a, o2b, oZ);

    const float thr = 0.10825317547305482f;  // sqrt(3)/16
    const float n0 = sqrtf(o0a * o0a + o1a * o1a + o2a * o2a);
    const float n1 = sqrtf(o0b * o0b + o1b * o1b + o2b * o2b);

    float* outb = out + (size_t)b * 3 * Nn;
    outb[j0]          = o0a + __ldg(grid_o + i0);
    outb[Nn + j0]     = o1a + __ldg(grid_o + Gn + i0);
    outb[2 * Nn + j0] = o2a + __ldg(grid_o + 2 * Gn + i0);
    outb[j1]          = o0b + __ldg(grid_o + i1);
    outb[Nn + j1]     = o1b + __ldg(grid_o + Gn + i1);
    outb[2 * Nn + j1] = o2b + __ldg(grid_o + 2 * Gn + i1);

    reg_out[b * Nn + j0] = fmaxf(n0 - thr, 0.f);
    reg_out[b * Nn + j1] = fmaxf(n1 - thr, 0.f);
}

extern "C" void kernel_launch(void* const* d_in, const int* in_sizes, int n_in,
                              void* d_out, int out_size)
{
    const float* x      = (const float*)d_in[0];
    const int*   counts = (const int*)  d_in[1];
    const float* b_rnd  = (const float*)d_in[2];
    const float* grid_o = (const float*)d_in[3];
    const float* W1     = (const float*)d_in[4];
    const float* b1     = (const float*)d_in[5];
    const float* W2     = (const float*)d_in[6];
    const float* b2     = (const float*)d_in[7];

    float* out     = (float*)d_out;              // (B, 3, N)
    float* reg_out = out + (size_t)Bn * 3 * Nn;  // (B, N)

    prep_kernel<<<Bn, TPB>>>(counts);
    mlp_kernel<<<Bn * (Nn / PPB), TPB>>>(x, b_rnd, grid_o, W1, b1, W2, b2,
                                         out, reg_out);
}

// round 3
// speedup vs baseline: 1.4795x; 1.0995x over previous
#include <cuda_runtime.h>

#define Bn 32
#define Cn 32
#define Gn 4096
#define Nn 16384
#define Hn 64
#define TPB 128
#define PPT 2
#define PPB (TPB * PPT)   // 256 points per block

typedef unsigned long long u64;

// per-batch inclusive cumsum of counts
__device__ int g_cum[Bn * Gn];

// ---- packed f32x2 helpers --------------------------------------------------
static __device__ __forceinline__ u64 pk(float lo, float hi) {
    u64 r; asm("mov.b64 %0, {%1, %2};" : "=l"(r) : "f"(lo), "f"(hi)); return r;
}
static __device__ __forceinline__ void upk(float& lo, float& hi, u64 v) {
    asm("mov.b64 {%0, %1}, %2;" : "=f"(lo), "=f"(hi) : "l"(v));
}
static __device__ __forceinline__ u64 fma2(u64 a, u64 b, u64 c) {
    u64 d; asm("fma.rn.f32x2 %0, %1, %2, %3;" : "=l"(d) : "l"(a), "l"(b), "l"(c));
    return d;
}

// ---- weight blob: staged in device mem, executed from constant mem ---------
struct __align__(16) WBlob {
    float w1p[Hn * 36];      // row h: W1[h][0..33], b1[h], 0   (144B rows, 16B aligned)
    ulonglong2 w2a[Hn];      // {pk(w0,w0), pk(w1,w1)}
    u64  w2b[Hn];            // pk(w2,w2)
    float b2v[4];
};
__device__   WBlob g_blob;   // staging (written by wtrans kernel)
__constant__ WBlob c_blob;   // read by mlp kernel via uniform constant port

// ---------------------------------------------------------------------------
// Kernel 0: transform weights into padded/fused layout (1 block).
// ---------------------------------------------------------------------------
__global__ void wtrans_kernel(const float* __restrict__ W1,
                              const float* __restrict__ b1,
                              const float* __restrict__ W2,
                              const float* __restrict__ b2)
{
    const int t = threadIdx.x;
    for (int i = t; i < Hn * 36; i += blockDim.x) {
        int h = i / 36, c = i % 36;
        float v;
        if (c < 34)      v = W1[h * 34 + c];
        else if (c == 34) v = b1[h];
        else              v = 0.f;
        g_blob.w1p[i] = v;
    }
    if (t < Hn) {
        float w0 = W2[t], w1 = W2[Hn + t], w2 = W2[2 * Hn + t];
        g_blob.w2a[t] = make_ulonglong2(pk(w0, w0), pk(w1, w1));
        g_blob.w2b[t] = pk(w2, w2);
    }
    if (t < 3) g_blob.b2v[t] = b2[t];
    if (t == 3) g_blob.b2v[3] = 0.f;
}

// ---------------------------------------------------------------------------
// Kernel 1: per-batch inclusive cumsum of counts -> g_cum. One block/batch.
// ---------------------------------------------------------------------------
__global__ __launch_bounds__(256) void prep_kernel(const int* __restrict__ counts)
{
    const int b = blockIdx.x;
    __shared__ int wsum[8];

    const int t    = threadIdx.x;
    const int lane = t & 31;
    const int w    = t >> 5;
    const int base = t * 16;

    int local[16];
    int s = 0;
#pragma unroll
    for (int i = 0; i < 16; i++) {
        s += counts[b * Gn + base + i];
        local[i] = s;
    }
    int v = s;
#pragma unroll
    for (int d = 1; d < 32; d <<= 1) {
        int u = __shfl_up_sync(0xffffffff, v, d);
        if (lane >= d) v += u;
    }
    if (lane == 31) wsum[w] = v;
    __syncthreads();
    int woff = 0;
    for (int i = 0; i < w; i++) woff += wsum[i];
    const int excl = woff + v - s;
#pragma unroll
    for (int i = 0; i < 16; i++) g_cum[b * Gn + base + i] = local[i] + excl;
}

// ---------------------------------------------------------------------------
// Kernel 2: searchsorted + gather + constant-weight packed MLP + epilogue.
// ---------------------------------------------------------------------------
__global__ __launch_bounds__(TPB, 5) void mlp_kernel(
    const float* __restrict__ x,       // (B, C, G)
    const float* __restrict__ b_rnd,   // (B, 2, N)
    const float* __restrict__ grid_o,  // (3, G)
    float* __restrict__ out,           // (B, 3, N)
    float* __restrict__ reg_out)       // (B, N)
{
    __shared__ int cums[Gn];                        // 16 KB

    const int t = threadIdx.x;
    const int blocksPerBatch = Nn / PPB;            // 64
    const int b    = blockIdx.x / blocksPerBatch;
    const int tile = blockIdx.x % blocksPerBatch;

#pragma unroll
    for (int i = t; i < Gn; i += TPB) cums[i] = g_cum[b * Gn + i];
    __syncthreads();

    const int j0 = tile * PPB + t;                  // point A
    const int j1 = j0 + TPB;                        // point B

    int i0, i1;
    {
        int lo = 0, hi = Gn;
        while (lo < hi) { int m = (lo + hi) >> 1; if (cums[m] > j0) hi = m; else lo = m + 1; }
        i0 = lo;
        lo = 0; hi = Gn;
        while (lo < hi) { int m = (lo + hi) >> 1; if (cums[m] > j1) hi = m; else lo = m + 1; }
        i1 = lo;
    }

    // gathered inputs packed over channel pairs; pair 16 = b_rnd, pair 17 = {1,0} (bias)
    u64 vp0[18], vp1[18];
    const float* xb = x + (size_t)b * Cn * Gn;
#pragma unroll
    for (int c = 0; c < 16; c++) {
        vp0[c] = pk(__ldg(xb + (2 * c) * Gn + i0), __ldg(xb + (2 * c + 1) * Gn + i0));
        vp1[c] = pk(__ldg(xb + (2 * c) * Gn + i1), __ldg(xb + (2 * c + 1) * Gn + i1));
    }
    const float* br = b_rnd + (size_t)b * 2 * Nn;
    vp0[16] = pk(br[j0], br[Nn + j0]);
    vp1[16] = pk(br[j1], br[Nn + j1]);
    const u64 onezero = pk(1.0f, 0.0f);
    vp0[17] = onezero;
    vp1[17] = onezero;

    u64 oX = pk(c_blob.b2v[0], c_blob.b2v[0]);   // {point A, point B}
    u64 oY = pk(c_blob.b2v[1], c_blob.b2v[1]);
    u64 oZ = pk(c_blob.b2v[2], c_blob.b2v[2]);

#pragma unroll 4
    for (int h = 0; h < Hn; h++) {
        const ulonglong2* wrow =
            reinterpret_cast<const ulonglong2*>(&c_blob.w1p[h * 36]);
        // 4 independent chains (2 per point)
        u64 a0A = 0ull, a0B = 0ull, a1A = 0ull, a1B = 0ull;
#pragma unroll
        for (int c = 0; c < 9; c++) {
            ulonglong2 wv = wrow[c];
            a0A = fma2(wv.x, vp0[2 * c],     a0A);
            a0B = fma2(wv.y, vp0[2 * c + 1], a0B);
            a1A = fma2(wv.x, vp1[2 * c],     a1A);
            a1B = fma2(wv.y, vp1[2 * c + 1], a1B);
        }
        float l0, h0, l0b, h0b, l1, h1, l1b, h1b;
        upk(l0, h0, a0A);  upk(l0b, h0b, a0B);
        upk(l1, h1, a1A);  upk(l1b, h1b, a1B);
        float act0 = fmaxf((l0 + h0) + (l0b + h0b), 0.f);
        float act1 = fmaxf((l1 + h1) + (l1b + h1b), 0.f);
        u64 act = pk(act0, act1);
        ulonglong2 w2p = c_blob.w2a[h];
        oX = fma2(w2p.x, act, oX);
        oY = fma2(w2p.y, act, oY);
        oZ = fma2(c_blob.w2b[h], act, oZ);
    }

    float o0a, o0b, o1a, o1b, o2a, o2b;
    upk(o0a, o0b, oX);
    upk(o1a, o1b, oY);
    upk(o2a, o2b, oZ);

    const float thr = 0.10825317547305482f;  // sqrt(3)/16
    const float n0 = sqrtf(o0a * o0a + o1a * o1a + o2a * o2a);
    const float n1 = sqrtf(o0b * o0b + o1b * o1b + o2b * o2b);

    float* outb = out + (size_t)b * 3 * Nn;
    outb[j0]          = o0a + __ldg(grid_o + i0);
    outb[Nn + j0]     = o1a + __ldg(grid_o + Gn + i0);
    outb[2 * Nn + j0] = o2a + __ldg(grid_o + 2 * Gn + i0);
    outb[j1]          = o0b + __ldg(grid_o + i1);
    outb[Nn + j1]     = o1b + __ldg(grid_o + Gn + i1);
    outb[2 * Nn + j1] = o2b + __ldg(grid_o + 2 * Gn + i1);

    reg_out[b * Nn + j0] = fmaxf(n0 - thr, 0.f);
    reg_out[b * Nn + j1] = fmaxf(n1 - thr, 0.f);
}

extern "C" void kernel_launch(void* const* d_in, const int* in_sizes, int n_in,
                              void* d_out, int out_size)
{
    const float* x      = (const float*)d_in[0];
    const int*   counts = (const int*)  d_in[1];
    const float* b_rnd  = (const float*)d_in[2];
    const float* grid_o = (const float*)d_in[3];
    const float* W1     = (const float*)d_in[4];
    const float* b1     = (const float*)d_in[5];
    const float* W2     = (const float*)d_in[6];
    const float* b2     = (const float*)d_in[7];

    float* out     = (float*)d_out;              // (B, 3, N)
    float* reg_out = out + (size_t)Bn * 3 * Nn;  // (B, N)

    wtrans_kernel<<<1, 256>>>(W1, b1, W2, b2);
    prep_kernel<<<Bn, 256>>>(counts);

    // copy staged blob into constant memory (graph-legal D2D memcpy node)
    void* c_addr = nullptr;
    void* g_addr = nullptr;
    cudaGetSymbolAddress(&c_addr, c_blob);
    cudaGetSymbolAddress(&g_addr, g_blob);
    cudaMemcpyAsync(c_addr, g_addr, sizeof(WBlob), cudaMemcpyDeviceToDevice);

    mlp_kernel<<<Bn * (Nn / PPB), TPB>>>(x, b_rnd, grid_o, out, reg_out);
}